// round 1
// baseline (speedup 1.0000x reference)
#include <cuda_runtime.h>
#include <math.h>

// Problem shape (fixed for this dataset entry): v0, v1 = [8192, 256] fp32.
// loss = mean_i ||v0_i - v1_i||  +  0.5 * sum_views mean_i [ log(sum_{j!=i} exp(-d_ij)) - log(N-1) ]
// d_ij = max(sqrt(max(|z_i|^2 + |z_j|^2 - 2 z_i.z_j, 0)), 1e-12)

namespace {
constexpr int N  = 8192;
constexpr int D  = 256;
constexpr int BM = 128;
constexpr int BN = 128;
constexpr int BK = 16;
constexpr int NTHREADS = 256;
constexpr int NJCH   = 16;           // j-chunks per view
constexpr int JCHUNK = N / NJCH;     // 512 columns per chunk
constexpr int NITILES = N / BM;      // 64
}

// Scratch (static device globals: no allocation in kernel_launch)
__device__ __align__(16) float g_sq[2][N];          // row squared norms per view
__device__ __align__(16) float g_alignRow[N];       // per-row L2 of (v0-v1)
__device__ __align__(16) float g_part[2][NJCH][N];  // partial row sums of exp(-d)

// ---------------------------------------------------------------------------
// Kernel 1: per-row squared norms + align row norms. One warp per row.
// ---------------------------------------------------------------------------
__global__ void prep_kernel(const float* __restrict__ v0, const float* __restrict__ v1) {
    int row  = blockIdx.x * blockDim.y + threadIdx.y;
    int lane = threadIdx.x;
    const float4* r0 = reinterpret_cast<const float4*>(v0 + (size_t)row * D);
    const float4* r1 = reinterpret_cast<const float4*>(v1 + (size_t)row * D);
    float s0 = 0.f, s1 = 0.f, sd = 0.f;
#pragma unroll
    for (int c = lane; c < D / 4; c += 32) {
        float4 a = r0[c], b = r1[c];
        s0 += a.x * a.x + a.y * a.y + a.z * a.z + a.w * a.w;
        s1 += b.x * b.x + b.y * b.y + b.z * b.z + b.w * b.w;
        float dx = a.x - b.x, dy = a.y - b.y, dz = a.z - b.z, dw = a.w - b.w;
        sd += dx * dx + dy * dy + dz * dz + dw * dw;
    }
#pragma unroll
    for (int off = 16; off > 0; off >>= 1) {
        s0 += __shfl_down_sync(0xffffffffu, s0, off);
        s1 += __shfl_down_sync(0xffffffffu, s1, off);
        sd += __shfl_down_sync(0xffffffffu, sd, off);
    }
    if (lane == 0) {
        g_sq[0][row]    = s0;
        g_sq[1][row]    = s1;
        g_alignRow[row] = sqrtf(sd);
    }
}

// ---------------------------------------------------------------------------
// Kernel 2: fused Gram + exp(-dist) row-sum.
// Block = (i-tile of 128 rows) x (j-chunk of 512 cols) for one view.
// Classic 128x128x16 SGEMM tiling, 8x8 register microtile, 256 threads.
// Epilogue folds d2 -> sqrt -> exp -> per-row sum; diagonal skipped.
// Each block writes its 128 partial row sums to a unique slice (deterministic).
// ---------------------------------------------------------------------------
__global__ __launch_bounds__(NTHREADS, 2)
void gram_kernel(const float* __restrict__ v0, const float* __restrict__ v1) {
    const int view = blockIdx.z;
    const float* __restrict__ z = view ? v1 : v0;
    const int i0     = blockIdx.x * BM;
    const int jch    = blockIdx.y;
    const int j0base = jch * JCHUNK;

    __shared__ float As[BK][BM + 4];
    __shared__ float Bs[BK][BN + 4];

    const int tid = threadIdx.x;
    const int tx  = tid & 15;   // 0..15  -> 8 columns each
    const int ty  = tid >> 4;   // 0..15  -> 8 rows each

    // Row squared norms for this thread's 8 rows (held in registers).
    float sqi[8];
    {
        const float4* p = reinterpret_cast<const float4*>(&g_sq[view][i0 + ty * 8]);
        float4 q0 = p[0], q1 = p[1];
        sqi[0] = q0.x; sqi[1] = q0.y; sqi[2] = q0.z; sqi[3] = q0.w;
        sqi[4] = q1.x; sqi[5] = q1.y; sqi[6] = q1.z; sqi[7] = q1.w;
    }

    float rsum[8];
#pragma unroll
    for (int m = 0; m < 8; m++) rsum[m] = 0.f;

    for (int jt = 0; jt < JCHUNK; jt += BN) {
        const int j0 = j0base + jt;

        float acc[8][8];
#pragma unroll
        for (int m = 0; m < 8; m++)
#pragma unroll
            for (int n = 0; n < 8; n++) acc[m][n] = 0.f;

        for (int kt = 0; kt < D; kt += BK) {
            // Load 128x16 tiles of A (rows i0..) and B (rows j0..), k-major in smem.
#pragma unroll
            for (int s = 0; s < 2; s++) {
                int idx = tid + s * 256;        // 0..511 float4 slots
                int r   = idx >> 2;             // row within tile 0..127
                int kv  = (idx & 3) * 4;        // k offset 0,4,8,12
                float4 a = *reinterpret_cast<const float4*>(&z[(size_t)(i0 + r) * D + kt + kv]);
                As[kv + 0][r] = a.x; As[kv + 1][r] = a.y;
                As[kv + 2][r] = a.z; As[kv + 3][r] = a.w;
                float4 b = *reinterpret_cast<const float4*>(&z[(size_t)(j0 + r) * D + kt + kv]);
                Bs[kv + 0][r] = b.x; Bs[kv + 1][r] = b.y;
                Bs[kv + 2][r] = b.z; Bs[kv + 3][r] = b.w;
            }
            __syncthreads();

#pragma unroll
            for (int kk = 0; kk < BK; kk++) {
                float4 a0 = *reinterpret_cast<const float4*>(&As[kk][ty * 8]);
                float4 a1 = *reinterpret_cast<const float4*>(&As[kk][ty * 8 + 4]);
                float4 b0 = *reinterpret_cast<const float4*>(&Bs[kk][tx * 8]);
                float4 b1 = *reinterpret_cast<const float4*>(&Bs[kk][tx * 8 + 4]);
                float av[8] = {a0.x, a0.y, a0.z, a0.w, a1.x, a1.y, a1.z, a1.w};
                float bv[8] = {b0.x, b0.y, b0.z, b0.w, b1.x, b1.y, b1.z, b1.w};
#pragma unroll
                for (int m = 0; m < 8; m++)
#pragma unroll
                    for (int n = 0; n < 8; n++)
                        acc[m][n] = fmaf(av[m], bv[n], acc[m][n]);
            }
            __syncthreads();
        }

        // Epilogue: d2 = sqi + sqj - 2*dot ; skip diagonal; rsum += exp(-d)
        float sqj[8];
        {
            const float4* p = reinterpret_cast<const float4*>(&g_sq[view][j0 + tx * 8]);
            float4 q0 = p[0], q1 = p[1];
            sqj[0] = q0.x; sqj[1] = q0.y; sqj[2] = q0.z; sqj[3] = q0.w;
            sqj[4] = q1.x; sqj[5] = q1.y; sqj[6] = q1.z; sqj[7] = q1.w;
        }
#pragma unroll
        for (int m = 0; m < 8; m++) {
            const int gi = i0 + ty * 8 + m;
            float acc_m = 0.f;
#pragma unroll
            for (int n = 0; n < 8; n++) {
                const int gj = j0 + tx * 8 + n;
                float d2 = sqi[m] + sqj[n] - 2.f * acc[m][n];
                d2 = fmaxf(d2, 0.f);
                float d = fmaxf(sqrtf(d2), 1e-12f);
                float e = __expf(-d);
                acc_m += (gi != gj) ? e : 0.f;
            }
            rsum[m] += acc_m;
        }
    }

    // Reduce rsum over the 16 tx lanes (consecutive lanes within a warp; width=16).
#pragma unroll
    for (int m = 0; m < 8; m++) {
        float v = rsum[m];
#pragma unroll
        for (int off = 8; off > 0; off >>= 1)
            v += __shfl_down_sync(0xffffffffu, v, off, 16);
        if (tx == 0) g_part[view][jch][i0 + ty * 8 + m] = v;
    }
}

// ---------------------------------------------------------------------------
// Kernel 3: finalize. fp64 accumulation to survive align/entropy cancellation.
// ---------------------------------------------------------------------------
__global__ void finalize_kernel(float* __restrict__ out) {
    __shared__ double sh0[256], sh1[256], sh2[256];
    const int tid = threadIdx.x;
    double a = 0.0, e0 = 0.0, e1 = 0.0;
    for (int i = tid; i < N; i += 256) {
        a += (double)g_alignRow[i];
        float s0 = 0.f, s1 = 0.f;
#pragma unroll
        for (int c = 0; c < NJCH; c++) {
            s0 += g_part[0][c][i];
            s1 += g_part[1][c][i];
        }
        e0 += log((double)s0);
        e1 += log((double)s1);
    }
    sh0[tid] = a; sh1[tid] = e0; sh2[tid] = e1;
    __syncthreads();
    for (int off = 128; off > 0; off >>= 1) {
        if (tid < off) {
            sh0[tid] += sh0[tid + off];
            sh1[tid] += sh1[tid + off];
            sh2[tid] += sh2[tid + off];
        }
        __syncthreads();
    }
    if (tid == 0) {
        const double inv_n = 1.0 / (double)N;
        const double logm  = log((double)(N - 1));
        double align   = sh0[0] * inv_n;
        double entropy = 0.5 * ((sh1[0] * inv_n - logm) + (sh2[0] * inv_n - logm));
        out[0] = (float)(align + entropy);
    }
}

// ---------------------------------------------------------------------------
extern "C" void kernel_launch(void* const* d_in, const int* in_sizes, int n_in,
                              void* d_out, int out_size) {
    const float* v0 = (const float*)d_in[0];
    const float* v1 = (const float*)d_in[1];
    float* out = (float*)d_out;

    prep_kernel<<<N / 8, dim3(32, 8)>>>(v0, v1);
    gram_kernel<<<dim3(NITILES, NJCH, 2), NTHREADS>>>(v0, v1);
    finalize_kernel<<<1, 256>>>(out);
}

// round 2
// speedup vs baseline: 1.7067x; 1.7067x over previous
#include <cuda_runtime.h>
#include <math.h>

// loss = mean_i ||v0_i - v1_i||  +  0.5 * sum_views mean_i [ log(sum_{j!=i} exp(-d_ij)) - log(N-1) ]
// d_ij = max(sqrt(max(|z_i|^2 + |z_j|^2 - 2 z_i.z_j, 0)), 1e-12)
// Symmetric: only upper-triangular 128x128 tiles are computed; each tile's
// exp values feed both its i-rows (row sums) and j-rows (column sums).

namespace {
constexpr int N  = 8192;
constexpr int D  = 256;
constexpr int BM = 128;
constexpr int BN = 128;
constexpr int BK = 16;
constexpr int NTHREADS = 256;
constexpr int NT = N / BM;                 // 64 tiles per dimension
constexpr int NTRI = NT * (NT + 1) / 2;    // 2080 upper-tri tiles per view
}

// Scratch (static device globals: no allocation in kernel_launch)
__device__ __align__(16) float g_sq[2][N];         // row squared norms per view
__device__ __align__(16) float g_alignRow[N];      // per-row L2 of (v0-v1)
__device__ __align__(16) float g_part[2][NT][N];   // partial row sums of exp(-d), slot = other tile index

// ---------------------------------------------------------------------------
// Kernel 1: per-row squared norms + align row norms. One warp per row.
// ---------------------------------------------------------------------------
__global__ void prep_kernel(const float* __restrict__ v0, const float* __restrict__ v1) {
    int row  = blockIdx.x * blockDim.y + threadIdx.y;
    int lane = threadIdx.x;
    const float4* r0 = reinterpret_cast<const float4*>(v0 + (size_t)row * D);
    const float4* r1 = reinterpret_cast<const float4*>(v1 + (size_t)row * D);
    float s0 = 0.f, s1 = 0.f, sd = 0.f;
#pragma unroll
    for (int c = lane; c < D / 4; c += 32) {
        float4 a = r0[c], b = r1[c];
        s0 += a.x * a.x + a.y * a.y + a.z * a.z + a.w * a.w;
        s1 += b.x * b.x + b.y * b.y + b.z * b.z + b.w * b.w;
        float dx = a.x - b.x, dy = a.y - b.y, dz = a.z - b.z, dw = a.w - b.w;
        sd += dx * dx + dy * dy + dz * dz + dw * dw;
    }
#pragma unroll
    for (int off = 16; off > 0; off >>= 1) {
        s0 += __shfl_down_sync(0xffffffffu, s0, off);
        s1 += __shfl_down_sync(0xffffffffu, s1, off);
        sd += __shfl_down_sync(0xffffffffu, sd, off);
    }
    if (lane == 0) {
        g_sq[0][row]    = s0;
        g_sq[1][row]    = s1;
        g_alignRow[row] = sqrtf(sd);
    }
}

// ---------------------------------------------------------------------------
// Kernel 2: symmetric fused Gram + exp(-dist) row/col sums.
// One block = one upper-triangular 128x128 tile (ti <= tj) of one view.
// Row sums  -> g_part[view][tj][rows of tile ti]
// Col sums  -> g_part[view][ti][rows of tile tj]   (only when ti < tj)
// ---------------------------------------------------------------------------
__global__ __launch_bounds__(NTHREADS, 2)
void gram_sym_kernel(const float* __restrict__ v0, const float* __restrict__ v1) {
    const int view = blockIdx.z;
    const float* __restrict__ z = view ? v1 : v0;

    // Linear index -> (ti, tj) with ti <= tj:  l = tj*(tj+1)/2 + ti
    const int l = blockIdx.x;
    int tj = (int)((sqrtf(8.f * (float)l + 1.f) - 1.f) * 0.5f);
    while ((tj + 1) * (tj + 2) / 2 <= l) ++tj;
    while (tj * (tj + 1) / 2 > l) --tj;
    const int ti = l - tj * (tj + 1) / 2;
    const int i0 = ti * BM;
    const int j0 = tj * BN;

    __shared__ float As[BK][BM + 4];
    __shared__ float Bs[BK][BN + 4];
    __shared__ float colred[16][BN];

    const int tid = threadIdx.x;
    const int tx  = tid & 15;   // 0..15 -> 8 columns each
    const int ty  = tid >> 4;   // 0..15 -> 8 rows each

    float sqi[8];
    {
        const float4* p = reinterpret_cast<const float4*>(&g_sq[view][i0 + ty * 8]);
        float4 q0 = p[0], q1 = p[1];
        sqi[0] = q0.x; sqi[1] = q0.y; sqi[2] = q0.z; sqi[3] = q0.w;
        sqi[4] = q1.x; sqi[5] = q1.y; sqi[6] = q1.z; sqi[7] = q1.w;
    }

    float acc[8][8];
#pragma unroll
    for (int m = 0; m < 8; m++)
#pragma unroll
        for (int n = 0; n < 8; n++) acc[m][n] = 0.f;

    for (int kt = 0; kt < D; kt += BK) {
#pragma unroll
        for (int s = 0; s < 2; s++) {
            int idx = tid + s * 256;        // 0..511 float4 slots
            int r   = idx >> 2;             // row within tile 0..127
            int kv  = (idx & 3) * 4;        // k offset 0,4,8,12
            float4 a = *reinterpret_cast<const float4*>(&z[(size_t)(i0 + r) * D + kt + kv]);
            As[kv + 0][r] = a.x; As[kv + 1][r] = a.y;
            As[kv + 2][r] = a.z; As[kv + 3][r] = a.w;
            float4 b = *reinterpret_cast<const float4*>(&z[(size_t)(j0 + r) * D + kt + kv]);
            Bs[kv + 0][r] = b.x; Bs[kv + 1][r] = b.y;
            Bs[kv + 2][r] = b.z; Bs[kv + 3][r] = b.w;
        }
        __syncthreads();

#pragma unroll
        for (int kk = 0; kk < BK; kk++) {
            float4 a0 = *reinterpret_cast<const float4*>(&As[kk][ty * 8]);
            float4 a1 = *reinterpret_cast<const float4*>(&As[kk][ty * 8 + 4]);
            float4 b0 = *reinterpret_cast<const float4*>(&Bs[kk][tx * 8]);
            float4 b1 = *reinterpret_cast<const float4*>(&Bs[kk][tx * 8 + 4]);
            float av[8] = {a0.x, a0.y, a0.z, a0.w, a1.x, a1.y, a1.z, a1.w};
            float bv[8] = {b0.x, b0.y, b0.z, b0.w, b1.x, b1.y, b1.z, b1.w};
#pragma unroll
            for (int m = 0; m < 8; m++)
#pragma unroll
                for (int n = 0; n < 8; n++)
                    acc[m][n] = fmaf(av[m], bv[n], acc[m][n]);
        }
        __syncthreads();
    }

    // Epilogue: e = exp(-d); accumulate row sums and column sums.
    float sqj[8];
    {
        const float4* p = reinterpret_cast<const float4*>(&g_sq[view][j0 + tx * 8]);
        float4 q0 = p[0], q1 = p[1];
        sqj[0] = q0.x; sqj[1] = q0.y; sqj[2] = q0.z; sqj[3] = q0.w;
        sqj[4] = q1.x; sqj[5] = q1.y; sqj[6] = q1.z; sqj[7] = q1.w;
    }

    float rsum[8], csum[8];
#pragma unroll
    for (int m = 0; m < 8; m++) { rsum[m] = 0.f; csum[m] = 0.f; }

#pragma unroll
    for (int m = 0; m < 8; m++) {
        const int gi = i0 + ty * 8 + m;
#pragma unroll
        for (int n = 0; n < 8; n++) {
            const int gj = j0 + tx * 8 + n;
            float d2 = sqi[m] + sqj[n] - 2.f * acc[m][n];
            d2 = fmaxf(d2, 0.f);
            float d = fmaxf(sqrtf(d2), 1e-12f);
            float e = (gi != gj) ? __expf(-d) : 0.f;
            rsum[m] += e;
            csum[n] += e;
        }
    }

    // Row sums: reduce over the 16 tx lanes (width-16 shfl), write slot tj.
#pragma unroll
    for (int m = 0; m < 8; m++) {
        float v = rsum[m];
#pragma unroll
        for (int off = 8; off > 0; off >>= 1)
            v += __shfl_down_sync(0xffffffffu, v, off, 16);
        if (tx == 0) g_part[view][tj][i0 + ty * 8 + m] = v;
    }

    // Column sums: reduce over the 16 ty groups via smem, write slot ti.
    if (ti != tj) {
#pragma unroll
        for (int n = 0; n < 8; n++) colred[ty][tx * 8 + n] = csum[n];
        __syncthreads();
        if (tid < BN) {
            float v = 0.f;
#pragma unroll
            for (int k = 0; k < 16; k++) v += colred[k][tid];
            g_part[view][ti][j0 + tid] = v;
        }
    }
}

// ---------------------------------------------------------------------------
// Kernel 3: finalize. fp64 accumulation to survive align/entropy cancellation.
// ---------------------------------------------------------------------------
__global__ void finalize_kernel(float* __restrict__ out) {
    __shared__ double sh0[256], sh1[256], sh2[256];
    const int tid = threadIdx.x;
    double a = 0.0, e0 = 0.0, e1 = 0.0;
    for (int i = tid; i < N; i += 256) {
        a += (double)g_alignRow[i];
        float s0 = 0.f, s1 = 0.f;
#pragma unroll
        for (int c = 0; c < NT; c++) {
            s0 += g_part[0][c][i];
            s1 += g_part[1][c][i];
        }
        e0 += log((double)s0);
        e1 += log((double)s1);
    }
    sh0[tid] = a; sh1[tid] = e0; sh2[tid] = e1;
    __syncthreads();
    for (int off = 128; off > 0; off >>= 1) {
        if (tid < off) {
            sh0[tid] += sh0[tid + off];
            sh1[tid] += sh1[tid + off];
            sh2[tid] += sh2[tid + off];
        }
        __syncthreads();
    }
    if (tid == 0) {
        const double inv_n = 1.0 / (double)N;
        const double logm  = log((double)(N - 1));
        double align   = sh0[0] * inv_n;
        double entropy = 0.5 * ((sh1[0] * inv_n - logm) + (sh2[0] * inv_n - logm));
        out[0] = (float)(align + entropy);
    }
}

// ---------------------------------------------------------------------------
extern "C" void kernel_launch(void* const* d_in, const int* in_sizes, int n_in,
                              void* d_out, int out_size) {
    const float* v0 = (const float*)d_in[0];
    const float* v1 = (const float*)d_in[1];
    float* out = (float*)d_out;

    prep_kernel<<<N / 8, dim3(32, 8)>>>(v0, v1);
    gram_sym_kernel<<<dim3(NTRI, 1, 2), NTHREADS>>>(v0, v1);
    finalize_kernel<<<1, 256>>>(out);
}

// round 4
// speedup vs baseline: 2.8452x; 1.6671x over previous
#include <cuda_runtime.h>
#include <cuda_bf16.h>
#include <math.h>
#include <stdint.h>

// loss = mean_i ||v0_i - v1_i|| + 0.5 * sum_views mean_i [ log(sum_{j!=i} exp(-d_ij)) - log(N-1) ]
// d_ij = max(sqrt(max(|zi|^2+|zj|^2-2 zi.zj, 0)), 1e-12)
//
// Gram via mma.sync bf16 two-term split: dot ~= hi*hi + hi*lo + lo*hi (fp32 accum).
// Symmetric: upper-tri 128x128 tiles only; each tile feeds row sums AND col sums.
// (tcgen05 unavailable: harness PTX target is sm_103 without the 'a' feature set.)

namespace {
constexpr int N  = 8192;
constexpr int D  = 256;
constexpr int BM = 128;
constexpr int NT = N / BM;               // 64
constexpr int NTRI = NT * (NT + 1) / 2;  // 2080

constexpr int KCHUNK  = 64;              // bf16 k per chunk
constexpr int NCHUNK  = D / KCHUNK;      // 4
constexpr int PITCHB  = 144;             // smem row pitch bytes (128 payload + 16 pad)
constexpr int TILEB   = BM * PITCHB;     // 18432 bytes per operand tile
constexpr int BUFB    = 4 * TILEB;       // Ah, Al, Bh, Bl = 73728 bytes
constexpr int SM_SQI  = 2 * BUFB;        // 147456
constexpr int SM_SQJ  = SM_SQI + 512;
constexpr int SM_ROW  = SM_SQJ + 512;    // 4 x 128 f32
constexpr int SM_COL  = SM_ROW + 2048;   // 2 x 128 f32
constexpr int SMEM_TOTAL = SM_COL + 1024;
}

__device__ __align__(16) __nv_bfloat16 g_hi[2][N][D];
__device__ __align__(16) __nv_bfloat16 g_lo[2][N][D];
__device__ __align__(16) float g_sq[2][N];
__device__ __align__(16) float g_alignRow[N];
__device__ __align__(16) float g_part[2][NT][N];

// ---------------- PTX helpers (stable ISA only: sm_80-class features) -------
__device__ __forceinline__ uint32_t smem_u32(const void* p) {
    uint32_t a;
    asm("{ .reg .u64 t; cvta.to.shared.u64 t, %1; cvt.u32.u64 %0, t; }" : "=r"(a) : "l"(p));
    return a;
}
__device__ __forceinline__ void cpasync16(uint32_t dst, const void* src) {
    asm volatile("cp.async.cg.shared.global [%0], [%1], 16;" :: "r"(dst), "l"(src) : "memory");
}
#define CP_COMMIT()  asm volatile("cp.async.commit_group;" ::: "memory")
#define CP_WAIT(n)   asm volatile("cp.async.wait_group %0;" :: "n"(n) : "memory")

__device__ __forceinline__ void ldsm4(uint32_t* r, uint32_t addr) {
    asm volatile("ldmatrix.sync.aligned.m8n8.x4.shared.b16 {%0,%1,%2,%3}, [%4];"
                 : "=r"(r[0]), "=r"(r[1]), "=r"(r[2]), "=r"(r[3]) : "r"(addr));
}
__device__ __forceinline__ void mma16816(float* c, const uint32_t* a, uint32_t b0, uint32_t b1) {
    asm volatile(
        "mma.sync.aligned.m16n8k16.row.col.f32.bf16.bf16.f32 "
        "{%0,%1,%2,%3}, {%4,%5,%6,%7}, {%8,%9}, {%0,%1,%2,%3};"
        : "+f"(c[0]), "+f"(c[1]), "+f"(c[2]), "+f"(c[3])
        : "r"(a[0]), "r"(a[1]), "r"(a[2]), "r"(a[3]), "r"(b0), "r"(b1));
}
__device__ __forceinline__ float fsqrt_approx(float x) {
    float r; asm("sqrt.approx.f32 %0, %1;" : "=f"(r) : "f"(x)); return r;
}

// ---------------------------------------------------------------------------
// Kernel 1: fp32 -> (hi, lo) bf16 split; squared norms; align row norms.
// ---------------------------------------------------------------------------
__global__ void convert_kernel(const float* __restrict__ v0, const float* __restrict__ v1) {
    int row  = blockIdx.x * blockDim.y + threadIdx.y;
    int lane = threadIdx.x;
    const float4* r0 = reinterpret_cast<const float4*>(v0 + (size_t)row * D);
    const float4* r1 = reinterpret_cast<const float4*>(v1 + (size_t)row * D);
    __nv_bfloat162* h0 = reinterpret_cast<__nv_bfloat162*>(&g_hi[0][row][0]);
    __nv_bfloat162* l0 = reinterpret_cast<__nv_bfloat162*>(&g_lo[0][row][0]);
    __nv_bfloat162* h1 = reinterpret_cast<__nv_bfloat162*>(&g_hi[1][row][0]);
    __nv_bfloat162* l1 = reinterpret_cast<__nv_bfloat162*>(&g_lo[1][row][0]);

    float s0 = 0.f, s1 = 0.f, sd = 0.f;
#pragma unroll
    for (int c = lane; c < D / 4; c += 32) {
        float4 a = r0[c], b = r1[c];
        s0 += a.x*a.x + a.y*a.y + a.z*a.z + a.w*a.w;
        s1 += b.x*b.x + b.y*b.y + b.z*b.z + b.w*b.w;
        float dx=a.x-b.x, dy=a.y-b.y, dz=a.z-b.z, dw=a.w-b.w;
        sd += dx*dx + dy*dy + dz*dz + dw*dw;
        {
            __nv_bfloat16 hx=__float2bfloat16(a.x), hy=__float2bfloat16(a.y);
            __nv_bfloat16 hz=__float2bfloat16(a.z), hw=__float2bfloat16(a.w);
            h0[2*c]   = __halves2bfloat162(hx, hy);
            h0[2*c+1] = __halves2bfloat162(hz, hw);
            l0[2*c]   = __halves2bfloat162(__float2bfloat16(a.x-__bfloat162float(hx)),
                                           __float2bfloat16(a.y-__bfloat162float(hy)));
            l0[2*c+1] = __halves2bfloat162(__float2bfloat16(a.z-__bfloat162float(hz)),
                                           __float2bfloat16(a.w-__bfloat162float(hw)));
        }
        {
            __nv_bfloat16 hx=__float2bfloat16(b.x), hy=__float2bfloat16(b.y);
            __nv_bfloat16 hz=__float2bfloat16(b.z), hw=__float2bfloat16(b.w);
            h1[2*c]   = __halves2bfloat162(hx, hy);
            h1[2*c+1] = __halves2bfloat162(hz, hw);
            l1[2*c]   = __halves2bfloat162(__float2bfloat16(b.x-__bfloat162float(hx)),
                                           __float2bfloat16(b.y-__bfloat162float(hy)));
            l1[2*c+1] = __halves2bfloat162(__float2bfloat16(b.z-__bfloat162float(hz)),
                                           __float2bfloat16(b.w-__bfloat162float(hw)));
        }
    }
#pragma unroll
    for (int off = 16; off > 0; off >>= 1) {
        s0 += __shfl_down_sync(0xffffffffu, s0, off);
        s1 += __shfl_down_sync(0xffffffffu, s1, off);
        sd += __shfl_down_sync(0xffffffffu, sd, off);
    }
    if (lane == 0) {
        g_sq[0][row] = s0;
        g_sq[1][row] = s1;
        g_alignRow[row] = sqrtf(sd);
    }
}

// ---------------------------------------------------------------------------
// Kernel 2: symmetric Gram + exp(-d) row/col sums via mma.sync bf16.
// One CTA = one upper-tri 128x128 tile of one view. 256 threads = 8 warps,
// warp grid 2(M) x 4(N), warp tile 64x32. Double-buffered cp.async K-chunks.
// ---------------------------------------------------------------------------
__global__ __launch_bounds__(256, 1)
void gram_mma_kernel() {
    extern __shared__ char smem[];
    const uint32_t sb = smem_u32(smem);
    const int tid = threadIdx.x;
    const int wid = tid >> 5;
    const int lid = tid & 31;
    const int wm = wid >> 2;          // 0..1
    const int wn = wid & 3;           // 0..3
    const int view = blockIdx.z;

    // tile decode: l = tj*(tj+1)/2 + ti, ti <= tj
    const int l = blockIdx.x;
    int tj = (int)((sqrtf(8.f * (float)l + 1.f) - 1.f) * 0.5f);
    while ((tj + 1) * (tj + 2) / 2 <= l) ++tj;
    while (tj * (tj + 1) / 2 > l) --tj;
    const int ti = l - tj * (tj + 1) / 2;
    const int i0 = ti * BM;
    const int j0 = tj * BM;

    const __nv_bfloat16* __restrict__ hiA = &g_hi[view][i0][0];
    const __nv_bfloat16* __restrict__ loA = &g_lo[view][i0][0];
    const __nv_bfloat16* __restrict__ hiB = &g_hi[view][j0][0];
    const __nv_bfloat16* __restrict__ loB = &g_lo[view][j0][0];

    float* sqi_s = reinterpret_cast<float*>(smem + SM_SQI);
    float* sqj_s = reinterpret_cast<float*>(smem + SM_SQJ);
    float* s_row = reinterpret_cast<float*>(smem + SM_ROW);   // [4][128]
    float* s_col = reinterpret_cast<float*>(smem + SM_COL);   // [2][128]
    if (tid < 128) {
        sqi_s[tid] = g_sq[view][i0 + tid];
        sqj_s[tid] = g_sq[view][j0 + tid];
    }

    // ---- async loader for one K-chunk into buffer b ----
    auto load_chunk = [&](int c, int b) {
        const int kt = c * KCHUNK;
        const uint32_t base = sb + b * BUFB;
#pragma unroll
        for (int it = 0; it < 16; it++) {
            const int t   = it >> 2;                 // operand tile 0..3 (const per it)
            const int rem = (it & 3) * 256 + tid;    // 0..1023
            const int row = rem >> 3;                // 0..127
            const int u   = rem & 7;                 // 16B unit in row
            const __nv_bfloat16* src =
                (t == 0 ? hiA : t == 1 ? loA : t == 2 ? hiB : loB)
                + (size_t)row * D + kt + u * 8;
            cpasync16(base + t * TILEB + row * PITCHB + u * 16, src);
        }
        CP_COMMIT();
    };

    // ldmatrix lane-invariant offsets
    const int rA = (lid & 7) | (((lid >> 3) & 1) << 3);  // row within 16
    const int cB = (lid >> 4) * 8;                       // col (k) within 16
    uint32_t aoff[4], boff[2];
#pragma unroll
    for (int mt = 0; mt < 4; mt++) aoff[mt] = (uint32_t)((wm*64 + mt*16 + rA) * PITCHB + cB*2);
#pragma unroll
    for (int np = 0; np < 2; np++) boff[np] = (uint32_t)((wn*32 + np*16 + rA) * PITCHB + cB*2);

    float acc[4][4][4];
#pragma unroll
    for (int a = 0; a < 4; a++)
#pragma unroll
        for (int b = 0; b < 4; b++)
#pragma unroll
            for (int q = 0; q < 4; q++) acc[a][b][q] = 0.f;

    load_chunk(0, 0);

    for (int c = 0; c < NCHUNK; c++) {
        const int b = c & 1;
        if (c + 1 < NCHUNK) load_chunk(c + 1, b ^ 1);
        if (c + 1 < NCHUNK) { CP_WAIT(1); } else { CP_WAIT(0); }
        __syncthreads();

        const uint32_t bAh = sb + b * BUFB + 0 * TILEB;
        const uint32_t bAl = sb + b * BUFB + 1 * TILEB;
        const uint32_t bBh = sb + b * BUFB + 2 * TILEB;
        const uint32_t bBl = sb + b * BUFB + 3 * TILEB;

#pragma unroll
        for (int ks = 0; ks < KCHUNK / 16; ks++) {
            const uint32_t ko = ks * 32;  // 16 bf16 cols = 32 bytes
            uint32_t Ah[4][4], Al[4][4], Bh[2][4], Bl[2][4];
#pragma unroll
            for (int mt = 0; mt < 4; mt++) {
                ldsm4(Ah[mt], bAh + aoff[mt] + ko);
                ldsm4(Al[mt], bAl + aoff[mt] + ko);
            }
#pragma unroll
            for (int np = 0; np < 2; np++) {
                ldsm4(Bh[np], bBh + boff[np] + ko);
                ldsm4(Bl[np], bBl + boff[np] + ko);
            }
#pragma unroll
            for (int mt = 0; mt < 4; mt++) {
#pragma unroll
                for (int nt = 0; nt < 4; nt++) {
                    const int np = nt >> 1, sel = nt & 1;
                    mma16816(acc[mt][nt], Ah[mt], Bh[np][sel], Bh[np][2 + sel]);
                    mma16816(acc[mt][nt], Ah[mt], Bl[np][sel], Bl[np][2 + sel]);
                    mma16816(acc[mt][nt], Al[mt], Bh[np][sel], Bh[np][2 + sel]);
                }
            }
        }
        __syncthreads();
    }

    // ---- Epilogue: e = exp(-d); row sums + col sums ----
    const bool diag = (ti == tj);
    float rsum[4][2], csum[4][2];
#pragma unroll
    for (int q = 0; q < 4; q++) { rsum[q][0]=rsum[q][1]=0.f; csum[q][0]=csum[q][1]=0.f; }

#pragma unroll
    for (int mt = 0; mt < 4; mt++) {
        const int r0 = wm*64 + mt*16 + (lid >> 2);  // local row (and +8)
        const float sqr0 = sqi_s[r0], sqr1 = sqi_s[r0 + 8];
#pragma unroll
        for (int nt = 0; nt < 4; nt++) {
            const int c0 = wn*32 + nt*8 + 2*(lid & 3);
            const float sqc0 = sqj_s[c0], sqc1 = sqj_s[c0 + 1];
            const float* a = acc[mt][nt];
            float d2, d, e00, e01, e10, e11;
            d2 = fmaxf(sqr0 + sqc0 - 2.f*a[0], 0.f); d = fmaxf(fsqrt_approx(d2), 1e-12f);
            e00 = (diag && r0 == c0) ? 0.f : __expf(-d);
            d2 = fmaxf(sqr0 + sqc1 - 2.f*a[1], 0.f); d = fmaxf(fsqrt_approx(d2), 1e-12f);
            e01 = (diag && r0 == c0 + 1) ? 0.f : __expf(-d);
            d2 = fmaxf(sqr1 + sqc0 - 2.f*a[2], 0.f); d = fmaxf(fsqrt_approx(d2), 1e-12f);
            e10 = (diag && r0 + 8 == c0) ? 0.f : __expf(-d);
            d2 = fmaxf(sqr1 + sqc1 - 2.f*a[3], 0.f); d = fmaxf(fsqrt_approx(d2), 1e-12f);
            e11 = (diag && r0 + 8 == c0 + 1) ? 0.f : __expf(-d);
            rsum[mt][0] += e00 + e01;
            rsum[mt][1] += e10 + e11;
            csum[nt][0] += e00 + e10;
            csum[nt][1] += e01 + e11;
        }
    }

    // Row sums: reduce over the 4 (lid&3) lanes (same rows).
#pragma unroll
    for (int mt = 0; mt < 4; mt++) {
        float v0 = rsum[mt][0], v1 = rsum[mt][1];
        v0 += __shfl_xor_sync(0xffffffffu, v0, 1); v0 += __shfl_xor_sync(0xffffffffu, v0, 2);
        v1 += __shfl_xor_sync(0xffffffffu, v1, 1); v1 += __shfl_xor_sync(0xffffffffu, v1, 2);
        if ((lid & 3) == 0) {
            const int r = wm*64 + mt*16 + (lid >> 2);
            s_row[wn*128 + r]     = v0;
            s_row[wn*128 + r + 8] = v1;
        }
    }
    // Col sums: reduce over the 8 (lid>>2) groups (same cols).
#pragma unroll
    for (int nt = 0; nt < 4; nt++) {
        float u0 = csum[nt][0], u1 = csum[nt][1];
#pragma unroll
        for (int off = 4; off < 32; off <<= 1) {
            u0 += __shfl_xor_sync(0xffffffffu, u0, off);
            u1 += __shfl_xor_sync(0xffffffffu, u1, off);
        }
        if (lid < 4) {
            const int cc = wn*32 + nt*8 + 2*lid;
            s_col[wm*128 + cc]     = u0;
            s_col[wm*128 + cc + 1] = u1;
        }
    }
    __syncthreads();

    if (tid < 128) {
        float rv = s_row[tid] + s_row[128 + tid] + s_row[256 + tid] + s_row[384 + tid];
        g_part[view][tj][i0 + tid] = rv;
        if (ti != tj) {
            float cv = s_col[tid] + s_col[128 + tid];
            g_part[view][ti][j0 + tid] = cv;
        }
    }
}

// ---------------------------------------------------------------------------
// Kernel 3: finalize with fp64 accumulation.
// ---------------------------------------------------------------------------
__global__ void finalize_kernel(float* __restrict__ out) {
    __shared__ double sh0[256], sh1[256], sh2[256];
    const int tid = threadIdx.x;
    double a = 0.0, e0 = 0.0, e1 = 0.0;
    for (int i = tid; i < N; i += 256) {
        a += (double)g_alignRow[i];
        float s0 = 0.f, s1 = 0.f;
#pragma unroll
        for (int c = 0; c < NT; c++) {
            s0 += g_part[0][c][i];
            s1 += g_part[1][c][i];
        }
        e0 += log((double)s0);
        e1 += log((double)s1);
    }
    sh0[tid] = a; sh1[tid] = e0; sh2[tid] = e1;
    __syncthreads();
    for (int off = 128; off > 0; off >>= 1) {
        if (tid < off) {
            sh0[tid] += sh0[tid + off];
            sh1[tid] += sh1[tid + off];
            sh2[tid] += sh2[tid + off];
        }
        __syncthreads();
    }
    if (tid == 0) {
        const double inv_n = 1.0 / (double)N;
        const double logm  = log((double)(N - 1));
        double align   = sh0[0] * inv_n;
        double entropy = 0.5 * ((sh1[0] * inv_n - logm) + (sh2[0] * inv_n - logm));
        out[0] = (float)(align + entropy);
    }
}

// ---------------------------------------------------------------------------
extern "C" void kernel_launch(void* const* d_in, const int* in_sizes, int n_in,
                              void* d_out, int out_size) {
    const float* v0 = (const float*)d_in[0];
    const float* v1 = (const float*)d_in[1];
    float* out = (float*)d_out;

    cudaFuncSetAttribute(gram_mma_kernel, cudaFuncAttributeMaxDynamicSharedMemorySize, SMEM_TOTAL);

    convert_kernel<<<N / 8, dim3(32, 8)>>>(v0, v1);
    gram_mma_kernel<<<dim3(NTRI, 1, 2), 256, SMEM_TOTAL>>>();
    finalize_kernel<<<1, 256>>>(out);
}

// round 5
// speedup vs baseline: 4.6511x; 1.6347x over previous
#include <cuda_runtime.h>
#include <cuda_bf16.h>
#include <math.h>
#include <stdint.h>

// loss = mean_i ||v0_i - v1_i|| + 0.5 * sum_views mean_i [ log(sum_{j!=i} exp(-d_ij)) - log(N-1) ]
// d_ij = max(sqrt(max(|zi|^2+|zj|^2-2 zi.zj, 0)), 1e-12)
//
// Gram via mma.sync pure bf16 (error budget: δd ~1e-3 -> rel_err on loss ~3e-5,
// well under the 1e-3 tolerance). Symmetric upper-tri 128x128 tiles, each tile
// feeds row sums AND col sums. 2 CTAs/SM for load/epilogue overlap.
// (tcgen05 unavailable: harness PTX target is sm_103 without the 'a' features.)

namespace {
constexpr int N  = 8192;
constexpr int D  = 256;
constexpr int BM = 128;
constexpr int NT = N / BM;               // 64
constexpr int NTRI = NT * (NT + 1) / 2;  // 2080

constexpr int KCHUNK  = 64;              // bf16 k per chunk
constexpr int NCHUNK  = D / KCHUNK;      // 4
constexpr int PITCHB  = 144;             // smem row pitch bytes (128 payload + 16 pad)
constexpr int TILEB   = BM * PITCHB;     // 18432 bytes per operand tile
constexpr int BUFB    = 2 * TILEB;       // A, B = 36864 bytes per stage
constexpr int SM_SQI  = 2 * BUFB;        // 73728
constexpr int SM_SQJ  = SM_SQI + 512;
constexpr int SM_ROW  = SM_SQJ + 512;    // 4 x 128 f32
constexpr int SM_COL  = SM_ROW + 2048;   // 2 x 128 f32
constexpr int SMEM_TOTAL = SM_COL + 1024;  // 77824 -> 2 CTAs/SM fits (<228KB)
}

__device__ __align__(16) __nv_bfloat16 g_hi[2][N][D];
__device__ __align__(16) float g_sq[2][N];
__device__ __align__(16) float g_alignRow[N];
__device__ __align__(16) float g_part[2][NT][N];

// ---------------- PTX helpers (stable ISA only) -----------------------------
__device__ __forceinline__ uint32_t smem_u32(const void* p) {
    uint32_t a;
    asm("{ .reg .u64 t; cvta.to.shared.u64 t, %1; cvt.u32.u64 %0, t; }" : "=r"(a) : "l"(p));
    return a;
}
__device__ __forceinline__ void cpasync16(uint32_t dst, const void* src) {
    asm volatile("cp.async.cg.shared.global [%0], [%1], 16;" :: "r"(dst), "l"(src) : "memory");
}
#define CP_COMMIT()  asm volatile("cp.async.commit_group;" ::: "memory")
#define CP_WAIT(n)   asm volatile("cp.async.wait_group %0;" :: "n"(n) : "memory")

__device__ __forceinline__ void ldsm4(uint32_t* r, uint32_t addr) {
    asm volatile("ldmatrix.sync.aligned.m8n8.x4.shared.b16 {%0,%1,%2,%3}, [%4];"
                 : "=r"(r[0]), "=r"(r[1]), "=r"(r[2]), "=r"(r[3]) : "r"(addr));
}
__device__ __forceinline__ void mma16816(float* c, const uint32_t* a, uint32_t b0, uint32_t b1) {
    asm volatile(
        "mma.sync.aligned.m16n8k16.row.col.f32.bf16.bf16.f32 "
        "{%0,%1,%2,%3}, {%4,%5,%6,%7}, {%8,%9}, {%0,%1,%2,%3};"
        : "+f"(c[0]), "+f"(c[1]), "+f"(c[2]), "+f"(c[3])
        : "r"(a[0]), "r"(a[1]), "r"(a[2]), "r"(a[3]), "r"(b0), "r"(b1));
}
__device__ __forceinline__ float fsqrt_approx(float x) {
    float r; asm("sqrt.approx.f32 %0, %1;" : "=f"(r) : "f"(x)); return r;
}

// ---------------------------------------------------------------------------
// Kernel 1: fp32 -> bf16; squared norms (fp32); align row norms.
// ---------------------------------------------------------------------------
__global__ void convert_kernel(const float* __restrict__ v0, const float* __restrict__ v1) {
    int row  = blockIdx.x * blockDim.y + threadIdx.y;
    int lane = threadIdx.x;
    const float4* r0 = reinterpret_cast<const float4*>(v0 + (size_t)row * D);
    const float4* r1 = reinterpret_cast<const float4*>(v1 + (size_t)row * D);
    __nv_bfloat162* h0 = reinterpret_cast<__nv_bfloat162*>(&g_hi[0][row][0]);
    __nv_bfloat162* h1 = reinterpret_cast<__nv_bfloat162*>(&g_hi[1][row][0]);

    float s0 = 0.f, s1 = 0.f, sd = 0.f;
#pragma unroll
    for (int c = lane; c < D / 4; c += 32) {
        float4 a = r0[c], b = r1[c];
        s0 += a.x*a.x + a.y*a.y + a.z*a.z + a.w*a.w;
        s1 += b.x*b.x + b.y*b.y + b.z*b.z + b.w*b.w;
        float dx=a.x-b.x, dy=a.y-b.y, dz=a.z-b.z, dw=a.w-b.w;
        sd += dx*dx + dy*dy + dz*dz + dw*dw;
        h0[2*c]   = __halves2bfloat162(__float2bfloat16(a.x), __float2bfloat16(a.y));
        h0[2*c+1] = __halves2bfloat162(__float2bfloat16(a.z), __float2bfloat16(a.w));
        h1[2*c]   = __halves2bfloat162(__float2bfloat16(b.x), __float2bfloat16(b.y));
        h1[2*c+1] = __halves2bfloat162(__float2bfloat16(b.z), __float2bfloat16(b.w));
    }
#pragma unroll
    for (int off = 16; off > 0; off >>= 1) {
        s0 += __shfl_down_sync(0xffffffffu, s0, off);
        s1 += __shfl_down_sync(0xffffffffu, s1, off);
        sd += __shfl_down_sync(0xffffffffu, sd, off);
    }
    if (lane == 0) {
        g_sq[0][row] = s0;
        g_sq[1][row] = s1;
        g_alignRow[row] = sqrtf(sd);
    }
}

// ---------------------------------------------------------------------------
// Kernel 2: symmetric Gram + exp(-d) row/col sums via mma.sync bf16.
// One CTA = one upper-tri 128x128 tile of one view. 256 threads = 8 warps,
// warp grid 2(M) x 4(N), warp tile 64x32. Double-buffered cp.async K-chunks.
// ---------------------------------------------------------------------------
__global__ __launch_bounds__(256, 2)
void gram_mma_kernel() {
    extern __shared__ char smem[];
    const uint32_t sb = smem_u32(smem);
    const int tid = threadIdx.x;
    const int wid = tid >> 5;
    const int lid = tid & 31;
    const int wm = wid >> 2;          // 0..1
    const int wn = wid & 3;           // 0..3
    const int view = blockIdx.z;

    // tile decode: l = tj*(tj+1)/2 + ti, ti <= tj
    const int l = blockIdx.x;
    int tj = (int)((sqrtf(8.f * (float)l + 1.f) - 1.f) * 0.5f);
    while ((tj + 1) * (tj + 2) / 2 <= l) ++tj;
    while (tj * (tj + 1) / 2 > l) --tj;
    const int ti = l - tj * (tj + 1) / 2;
    const int i0 = ti * BM;
    const int j0 = tj * BM;

    const __nv_bfloat16* __restrict__ hiA = &g_hi[view][i0][0];
    const __nv_bfloat16* __restrict__ hiB = &g_hi[view][j0][0];

    float* sqi_s = reinterpret_cast<float*>(smem + SM_SQI);
    float* sqj_s = reinterpret_cast<float*>(smem + SM_SQJ);
    float* s_row = reinterpret_cast<float*>(smem + SM_ROW);   // [4][128]
    float* s_col = reinterpret_cast<float*>(smem + SM_COL);   // [2][128]
    if (tid < 128) {
        sqi_s[tid] = g_sq[view][i0 + tid];
        sqj_s[tid] = g_sq[view][j0 + tid];
    }

    // ---- async loader for one K-chunk into buffer b ----
    auto load_chunk = [&](int c, int b) {
        const int kt = c * KCHUNK;
        const uint32_t base = sb + b * BUFB;
#pragma unroll
        for (int it = 0; it < 8; it++) {
            const int t   = it >> 2;                 // operand 0=A, 1=B
            const int rem = (it & 3) * 256 + tid;    // 0..1023
            const int row = rem >> 3;                // 0..127
            const int u   = rem & 7;                 // 16B unit in row
            const __nv_bfloat16* src = (t == 0 ? hiA : hiB) + (size_t)row * D + kt + u * 8;
            cpasync16(base + t * TILEB + row * PITCHB + u * 16, src);
        }
        CP_COMMIT();
    };

    // ldmatrix lane-invariant offsets
    const int rA = (lid & 7) | (((lid >> 3) & 1) << 3);  // row within 16
    const int cB = (lid >> 4) * 8;                       // col (k) within 16
    uint32_t aoff[4], boff[2];
#pragma unroll
    for (int mt = 0; mt < 4; mt++) aoff[mt] = (uint32_t)((wm*64 + mt*16 + rA) * PITCHB + cB*2);
#pragma unroll
    for (int np = 0; np < 2; np++) boff[np] = (uint32_t)((wn*32 + np*16 + rA) * PITCHB + cB*2);

    float acc[4][4][4];
#pragma unroll
    for (int a = 0; a < 4; a++)
#pragma unroll
        for (int b = 0; b < 4; b++)
#pragma unroll
            for (int q = 0; q < 4; q++) acc[a][b][q] = 0.f;

    load_chunk(0, 0);

    for (int c = 0; c < NCHUNK; c++) {
        const int b = c & 1;
        if (c + 1 < NCHUNK) load_chunk(c + 1, b ^ 1);
        if (c + 1 < NCHUNK) { CP_WAIT(1); } else { CP_WAIT(0); }
        __syncthreads();

        const uint32_t bA = sb + b * BUFB + 0 * TILEB;
        const uint32_t bB = sb + b * BUFB + 1 * TILEB;

#pragma unroll
        for (int ks = 0; ks < KCHUNK / 16; ks++) {
            const uint32_t ko = ks * 32;  // 16 bf16 cols = 32 bytes
            uint32_t A[4][4], B[2][4];
#pragma unroll
            for (int mt = 0; mt < 4; mt++) ldsm4(A[mt], bA + aoff[mt] + ko);
#pragma unroll
            for (int np = 0; np < 2; np++) ldsm4(B[np], bB + boff[np] + ko);
#pragma unroll
            for (int mt = 0; mt < 4; mt++) {
#pragma unroll
                for (int nt = 0; nt < 4; nt++) {
                    const int np = nt >> 1, sel = nt & 1;
                    mma16816(acc[mt][nt], A[mt], B[np][sel], B[np][2 + sel]);
                }
            }
        }
        __syncthreads();
    }

    // ---- Epilogue: e = exp(-d); row sums + col sums ----
    const bool diag = (ti == tj);
    float rsum[4][2], csum[4][2];
#pragma unroll
    for (int q = 0; q < 4; q++) { rsum[q][0]=rsum[q][1]=0.f; csum[q][0]=csum[q][1]=0.f; }

#pragma unroll
    for (int mt = 0; mt < 4; mt++) {
        const int r0 = wm*64 + mt*16 + (lid >> 2);  // local row (and +8)
        const float sqr0 = sqi_s[r0], sqr1 = sqi_s[r0 + 8];
#pragma unroll
        for (int nt = 0; nt < 4; nt++) {
            const int c0 = wn*32 + nt*8 + 2*(lid & 3);
            const float sqc0 = sqj_s[c0], sqc1 = sqj_s[c0 + 1];
            const float* a = acc[mt][nt];
            float d2, d, e00, e01, e10, e11;
            d2 = fmaxf(sqr0 + sqc0 - 2.f*a[0], 0.f); d = fmaxf(fsqrt_approx(d2), 1e-12f);
            e00 = (diag && r0 == c0) ? 0.f : __expf(-d);
            d2 = fmaxf(sqr0 + sqc1 - 2.f*a[1], 0.f); d = fmaxf(fsqrt_approx(d2), 1e-12f);
            e01 = (diag && r0 == c0 + 1) ? 0.f : __expf(-d);
            d2 = fmaxf(sqr1 + sqc0 - 2.f*a[2], 0.f); d = fmaxf(fsqrt_approx(d2), 1e-12f);
            e10 = (diag && r0 + 8 == c0) ? 0.f : __expf(-d);
            d2 = fmaxf(sqr1 + sqc1 - 2.f*a[3], 0.f); d = fmaxf(fsqrt_approx(d2), 1e-12f);
            e11 = (diag && r0 + 8 == c0 + 1) ? 0.f : __expf(-d);
            rsum[mt][0] += e00 + e01;
            rsum[mt][1] += e10 + e11;
            csum[nt][0] += e00 + e10;
            csum[nt][1] += e01 + e11;
        }
    }

    // Row sums: reduce over the 4 (lid&3) lanes (same rows).
#pragma unroll
    for (int mt = 0; mt < 4; mt++) {
        float v0 = rsum[mt][0], v1 = rsum[mt][1];
        v0 += __shfl_xor_sync(0xffffffffu, v0, 1); v0 += __shfl_xor_sync(0xffffffffu, v0, 2);
        v1 += __shfl_xor_sync(0xffffffffu, v1, 1); v1 += __shfl_xor_sync(0xffffffffu, v1, 2);
        if ((lid & 3) == 0) {
            const int r = wm*64 + mt*16 + (lid >> 2);
            s_row[wn*128 + r]     = v0;
            s_row[wn*128 + r + 8] = v1;
        }
    }
    // Col sums: reduce over the 8 (lid>>2) groups (same cols).
#pragma unroll
    for (int nt = 0; nt < 4; nt++) {
        float u0 = csum[nt][0], u1 = csum[nt][1];
#pragma unroll
        for (int off = 4; off < 32; off <<= 1) {
            u0 += __shfl_xor_sync(0xffffffffu, u0, off);
            u1 += __shfl_xor_sync(0xffffffffu, u1, off);
        }
        if (lid < 4) {
            const int cc = wn*32 + nt*8 + 2*lid;
            s_col[wm*128 + cc]     = u0;
            s_col[wm*128 + cc + 1] = u1;
        }
    }
    __syncthreads();

    if (tid < 128) {
        float rv = s_row[tid] + s_row[128 + tid] + s_row[256 + tid] + s_row[384 + tid];
        g_part[view][tj][i0 + tid] = rv;
        if (ti != tj) {
            float cv = s_col[tid] + s_col[128 + tid];
            g_part[view][ti][j0 + tid] = cv;
        }
    }
}

// ---------------------------------------------------------------------------
// Kernel 3: finalize with fp64 accumulation.
// ---------------------------------------------------------------------------
__global__ void finalize_kernel(float* __restrict__ out) {
    __shared__ double sh0[256], sh1[256], sh2[256];
    const int tid = threadIdx.x;
    double a = 0.0, e0 = 0.0, e1 = 0.0;
    for (int i = tid; i < N; i += 256) {
        a += (double)g_alignRow[i];
        float s0 = 0.f, s1 = 0.f;
#pragma unroll
        for (int c = 0; c < NT; c++) {
            s0 += g_part[0][c][i];
            s1 += g_part[1][c][i];
        }
        e0 += log((double)s0);
        e1 += log((double)s1);
    }
    sh0[tid] = a; sh1[tid] = e0; sh2[tid] = e1;
    __syncthreads();
    for (int off = 128; off > 0; off >>= 1) {
        if (tid < off) {
            sh0[tid] += sh0[tid + off];
            sh1[tid] += sh1[tid + off];
            sh2[tid] += sh2[tid + off];
        }
        __syncthreads();
    }
    if (tid == 0) {
        const double inv_n = 1.0 / (double)N;
        const double logm  = log((double)(N - 1));
        double align   = sh0[0] * inv_n;
        double entropy = 0.5 * ((sh1[0] * inv_n - logm) + (sh2[0] * inv_n - logm));
        out[0] = (float)(align + entropy);
    }
}

// ---------------------------------------------------------------------------
extern "C" void kernel_launch(void* const* d_in, const int* in_sizes, int n_in,
                              void* d_out, int out_size) {
    const float* v0 = (const float*)d_in[0];
    const float* v1 = (const float*)d_in[1];
    float* out = (float*)d_out;

    cudaFuncSetAttribute(gram_mma_kernel, cudaFuncAttributeMaxDynamicSharedMemorySize, SMEM_TOTAL);

    convert_kernel<<<N / 8, dim3(32, 8)>>>(v0, v1);
    gram_mma_kernel<<<dim3(NTRI, 1, 2), 256, SMEM_TOTAL>>>();
    finalize_kernel<<<1, 256>>>(out);
}